// round 14
// baseline (speedup 1.0000x reference)
#include <cuda_runtime.h>

// ---------------- problem constants ----------------
constexpr int P    = 10000;
constexpr int NPN  = 50;
constexpr int EPN  = 200;
constexpr int IN   = 64;
constexpr int HE   = 256;
constexpr int C2   = 64;
constexpr int RD   = 128;
constexpr int HM   = 256;
constexpr int OUTC = 16;
constexpr int EM   = 160000;
constexpr float EPSV  = 1e-5f;
constexpr float SLOPE = 0.01f;
constexpr int TPB  = 512;   // patch kernel threads; ONE CTA handles TWO patches

// ---------------- packed fp32x2 helpers (sm_103a) ----------------
typedef unsigned long long u64;
#define FMA2(d, a, b, c) asm("fma.rn.f32x2 %0, %1, %2, %3;" : "=l"(d) : "l"(a), "l"(b), "l"(c))
#define MUL2(d, a, b)    asm("mul.rn.f32x2 %0, %1, %2;"     : "=l"(d) : "l"(a), "l"(b))
#define ADD2(d, a, b)    asm("add.rn.f32x2 %0, %1, %2;"     : "=l"(d) : "l"(a), "l"(b))
#define DUP2(d, x)       asm("mov.b64 %0, {%1, %1};"        : "=l"(d) : "r"(__float_as_uint(x)))

// ---------------- device scratch ----------------
__device__ float  gEmb[P * RD];
__device__ int    gCntOut[P], gCntIn[P], gFill[P];
__device__ int    gOffs[P + 1];
__device__ float  gRsOut[P], gRsIn[P];
__device__ int    gSrtSrc[EM];
__device__ float  gSrtW[EM];
__device__ float  gAgg1[P * RD];
__device__ float  gAgg2[P * HM];
__device__ float  gH[P * HM];
__device__ float  gH2[P * HM];
__device__ double gSums[2 * HM], gSums2[2 * HM], gRoSum[2 * HM];
__device__ float  gScale[2 * HM], gShift[2 * HM];

// ---------------- patch kernel smem layout (float indices) ----------------
// Two patches per CTA. Patch tiles are CONTIGUOUS along rows so the GEMMs
// treat both patches as one taller matrix.
constexpr int H1S  = 264;                   // padded h1 row stride
constexpr int SH1  = 0;                     // h1 [128 x 264]: A rows 0..55 (56-63 zero),
                                            //                 B rows 64..119 (120-127 zero)
constexpr int ST   = 128 * H1S;             // t1 [112x64] / t2 [128x64] / scratch (8192 f)
constexpr int SFT  = ST + 128 * 64;         // feat [2 x 50 x 64]; later u [2 x 50 x 64]
constexpr int SEW  = SFT + 2 * 3200;        // raw edge weights [2x200]
constexpr int SRTW = SEW + 2 * EPN;         // sorted weights [2x200]
constexpr int SRSO = SRTW + 2 * EPN;        // rsqrt deg_out [2x50]
constexpr int SRSI = SRSO + 2 * NPN;        // rsqrt deg_in  [2x50]
constexpr int SRV  = SRSI + 2 * NPN;        // rvec per patch: r0[64] r1[256] r2[64] -> [2x384]
constexpr int SGA  = SRV + 2 * 384;         // scale [2x256]; later mu/inv [2x2]
constexpr int SGB  = SGA + 2 * HE;          // shift [2x256]
constexpr int SRED = SGB + 2 * HE;          // emb [2x128]
constexpr int SINT = SRED + 2 * RD;
constexpr int NI_SSRC = 0;                  // [2x200]
constexpr int NI_SDST = 2 * EPN;            // [2x200]
constexpr int NI_SRTS = 4 * EPN;            // [2x200]
constexpr int NI_START = 6 * EPN;           // [2x51]
constexpr int NI_FILL  = NI_START + 2 * (NPN + 1);  // [2x50]
constexpr int NI_CIN   = NI_FILL + 2 * NPN;         // [2x50]
constexpr int NI_COUT  = NI_CIN + 2 * NPN;          // [2x50]
constexpr int NINTS    = NI_COUT + 2 * NPN;
constexpr int SMEM_PATCH = (SINT + NINTS) * 4;      // ~208 KB -> 1 CTA/SM

// =====================================================================
// Patch embedder: one CTA per TWO patches, 512 threads, 128 regs.
// =====================================================================
__global__ void __launch_bounds__(TPB, 1) patch_kernel(
    const float* __restrict__ feats, const int* __restrict__ srcs,
    const int* __restrict__ dsts, const float* __restrict__ ews,
    const float* __restrict__ W1, const float* __restrict__ g1,
    const float* __restrict__ b1, const float* __restrict__ W2,
    const float* __restrict__ g2, const float* __restrict__ b2,
    const float* __restrict__ We)
{
    extern __shared__ float sm[];
    int* smi    = (int*)(sm + SINT);
    int* ssrc   = smi + NI_SSRC;
    int* sdst   = smi + NI_SDST;
    int* srts   = smi + NI_SRTS;
    int* sstart = smi + NI_START;
    int* sfill  = smi + NI_FILL;
    int* scin   = smi + NI_CIN;
    int* scout  = smi + NI_COUT;
    const int p0 = blockIdx.x * 2, t = threadIdx.x;

    // load both patches' edges (contiguous in global) + feats
    for (int i = t; i < 2 * EPN; i += TPB) {
        ssrc[i] = srcs[p0 * EPN + i];
        sdst[i] = dsts[p0 * EPN + i];
        sm[SEW + i] = ews[p0 * EPN + i];
    }
    {
        const float4* f4 = (const float4*)(feats + (long long)p0 * NPN * IN);
        float4* s4 = (float4*)(sm + SFT);
        for (int i = t; i < 2 * NPN * IN / 4; i += TPB) s4[i] = f4[i];
    }
    for (int i = t; i < 2 * NPN; i += TPB) { scin[i] = 0; scout[i] = 0; sfill[i] = 0; }
    // zero h1 pad rows 56-63 and 120-127
    for (int i = t; i < 16 * H1S; i += TPB) {
        int r = i / H1S, c = i - r * H1S;
        int rr = (r < 8) ? (56 + r) : (112 + r);
        sm[SH1 + rr * H1S + c] = 0.f;
    }
    __syncthreads();

    if (t < 2 * EPN) {
        int ph = (t >= EPN);
        atomicAdd(&scout[ph * NPN + ssrc[t]], 1);
        atomicAdd(&scin[ph * NPN + sdst[t]], 1);
    }
    __syncthreads();
    if (t < 2 * NPN) {
        sm[SRSO + t] = rsqrtf((float)(scout[t] > 0 ? scout[t] : 1));
        sm[SRSI + t] = rsqrtf((float)(scin[t]  > 0 ? scin[t]  : 1));
    }
    if (t >= TPB - 2) {  // serial per-patch scans (2 threads)
        int ph = t - (TPB - 2);
        int s = 0;
        for (int n = 0; n < NPN; n++) { sstart[ph * 51 + n] = s; s += scin[ph * NPN + n]; }
        sstart[ph * 51 + NPN] = s;
    }
    if (t < 2 * IN) {  // r0 per patch
        int ph = t >> 6, c = t & 63;
        float s = 0.f;
        for (int n = 0; n < NPN; n++) s += sm[SFT + ph * 3200 + n * IN + c];
        sm[SRV + ph * 384 + c] = s * (1.f / NPN);
    }
    __syncthreads();

    if (t < 2 * EPN) {  // counting sort by dst per patch
        int ph = (t >= EPN);
        int d = sdst[t];
        int pos = sstart[ph * 51 + d] + atomicAdd(&sfill[ph * NPN + d], 1);
        srts[ph * EPN + pos] = ssrc[t];
        sm[SRTW + ph * EPN + pos] = sm[SEW + t] * sm[SRSO + ph * NPN + ssrc[t]];
    }
    __syncthreads();

    // gconv1 gather (4 ch/thread): t1[112 x 64]; local rows >= 50 zero
    for (int i = t; i < 112 * 16; i += TPB) {
        int n = i >> 4, cp = (i & 15) << 2;
        int ph = (n >= 56), ln = n - 56 * ph;
        u64 a0 = 0ull, a1 = 0ull;
        if (ln < NPN) {
            int e1 = sstart[ph * 51 + ln + 1];
            for (int e = sstart[ph * 51 + ln]; e < e1; ++e) {
                int s = srts[ph * EPN + e];
                u64 ww; DUP2(ww, sm[SRTW + ph * EPN + e]);
                ulonglong2 x = *(const ulonglong2*)(sm + SFT + ph * 3200 + s * IN + cp);
                FMA2(a0, x.x, ww, a0);
                FMA2(a1, x.y, ww, a1);
            }
            u64 rr; DUP2(rr, sm[SRSI + ph * NPN + ln]);
            MUL2(a0, a0, rr);
            MUL2(a1, a1, rr);
        }
        ulonglong2 o; o.x = a0; o.y = a1;
        *(ulonglong2*)(sm + ST + n * IN + cp) = o;
    }
    __syncthreads();

    // GEMM1: h1[112 rows] = t1[112x64] @ W1[64x256]; W loaded once serves both patches.
    // 64 colg x 8 rowg x 14 rows (rg + 8j). Output row shifted +8 for patch B.
    {
        int c0 = (t & 63) * 4, rg = t >> 6;
        u64 a0[14], a1[14];
        #pragma unroll
        for (int j = 0; j < 14; j++) { a0[j] = 0ull; a1[j] = 0ull; }
        for (int k4 = 0; k4 < IN / 4; k4++) {
            int k = k4 * 4;
            ulonglong2 w0 = __ldg((const ulonglong2*)(W1 + (k + 0) * HE + c0));
            ulonglong2 w1 = __ldg((const ulonglong2*)(W1 + (k + 1) * HE + c0));
            ulonglong2 w2 = __ldg((const ulonglong2*)(W1 + (k + 2) * HE + c0));
            ulonglong2 w3 = __ldg((const ulonglong2*)(W1 + (k + 3) * HE + c0));
            #pragma unroll
            for (int j = 0; j < 14; j++) {
                float4 x = *(const float4*)(sm + ST + (rg + j * 8) * IN + k);
                u64 d;
                DUP2(d, x.x); FMA2(a0[j], d, w0.x, a0[j]); FMA2(a1[j], d, w0.y, a1[j]);
                DUP2(d, x.y); FMA2(a0[j], d, w1.x, a0[j]); FMA2(a1[j], d, w1.y, a1[j]);
                DUP2(d, x.z); FMA2(a0[j], d, w2.x, a0[j]); FMA2(a1[j], d, w2.y, a1[j]);
                DUP2(d, x.w); FMA2(a0[j], d, w3.x, a0[j]); FMA2(a1[j], d, w3.y, a1[j]);
            }
        }
        #pragma unroll
        for (int j = 0; j < 14; j++) {
            int r = rg + j * 8;
            int hr = r + ((r >= 56) ? 8 : 0);
            ulonglong2 o; o.x = a0[j]; o.y = a1[j];
            *(ulonglong2*)(sm + SH1 + hr * H1S + c0) = o;
        }
    }
    __syncthreads();

    // ---- layer-1 norm: exactly 512 (patch, channel) threads ----
    {
        int ph = t >> 8, c = t & 255;
        const float* row = sm + SH1 + (ph * 64) * H1S + c;
        float s = 0.f, s2 = 0.f;
        for (int n = 0; n < NPN; n++) {
            float v = row[n * H1S];
            s += v; s2 = fmaf(v, v, s2);
        }
        float mu = s * (1.f / NPN), var = s2 * (1.f / NPN) - mu * mu;
        float sc = g1[c] * rsqrtf(var + EPSV);
        sm[SGA + ph * HE + c] = sc;
        sm[SGB + ph * HE + c] = b1[c] - mu * sc;
    }
    __syncthreads();
    {   // apply + lrelu + r1 in one pass
        int ph = t >> 8, c = t & 255;
        float sc = sm[SGA + ph * HE + c], sh = sm[SGB + ph * HE + c];
        float* row = sm + SH1 + (ph * 64) * H1S + c;
        float s = 0.f;
        for (int n = 0; n < NPN; n++) {
            float v = fmaf(row[n * H1S], sc, sh);
            v = v >= 0.f ? v : SLOPE * v;
            row[n * H1S] = v;
            s += v;
        }
        sm[SRV + ph * 384 + 64 + c] = s * (1.f / NPN);
    }
    __syncthreads();

    // GEMM2: t2[128x64] = h1[128x264] @ W2[256x64]
    // 16 colg x 8 rowg x 16 rows x 4-way lane-K-split (interleaved comb).
    {
        int lane = t & 31, w = t >> 5;
        int ks   = (lane >> 3) & 3;
        int c0   = ((lane & 7) | ((w & 1) << 3)) * 4;
        int rg   = w >> 1;                          // 0..7; rows rg + 8j, j<16
        u64 a0[16], a1[16];
        #pragma unroll
        for (int j = 0; j < 16; j++) { a0[j] = 0ull; a1[j] = 0ull; }
        const float* px = sm + SH1 + rg * H1S + ks * 4;
        const float* pw = W2 + (ks * 4) * C2 + c0;
        #pragma unroll
        for (int i4 = 0; i4 < 16; i4++) {
            ulonglong2 w0 = __ldg((const ulonglong2*)(pw));
            ulonglong2 w1 = __ldg((const ulonglong2*)(pw + C2));
            ulonglong2 w2 = __ldg((const ulonglong2*)(pw + 2 * C2));
            ulonglong2 w3 = __ldg((const ulonglong2*)(pw + 3 * C2));
            #pragma unroll
            for (int j = 0; j < 16; j++) {
                float4 x = *(const float4*)(px + 8 * j * H1S);
                u64 d;
                DUP2(d, x.x); FMA2(a0[j], d, w0.x, a0[j]); FMA2(a1[j], d, w0.y, a1[j]);
                DUP2(d, x.y); FMA2(a0[j], d, w1.x, a0[j]); FMA2(a1[j], d, w1.y, a1[j]);
                DUP2(d, x.z); FMA2(a0[j], d, w2.x, a0[j]); FMA2(a1[j], d, w2.y, a1[j]);
                DUP2(d, x.w); FMA2(a0[j], d, w3.x, a0[j]); FMA2(a1[j], d, w3.y, a1[j]);
            }
            px += 16;
            pw += 16 * C2;
        }
        #pragma unroll
        for (int j = 0; j < 16; j++) {
            float2 v0 = *(float2*)&a0[j];
            float2 v1 = *(float2*)&a1[j];
            v0.x += __shfl_xor_sync(0xffffffffu, v0.x, 8);
            v0.y += __shfl_xor_sync(0xffffffffu, v0.y, 8);
            v1.x += __shfl_xor_sync(0xffffffffu, v1.x, 8);
            v1.y += __shfl_xor_sync(0xffffffffu, v1.y, 8);
            v0.x += __shfl_xor_sync(0xffffffffu, v0.x, 16);
            v0.y += __shfl_xor_sync(0xffffffffu, v0.y, 16);
            v1.x += __shfl_xor_sync(0xffffffffu, v1.x, 16);
            v1.y += __shfl_xor_sync(0xffffffffu, v1.y, 16);
            if (ks == 0) {
                float4 o = make_float4(v0.x, v0.y, v1.x, v1.y);
                *(float4*)(sm + ST + (rg + 8 * j) * C2 + c0) = o;
            }
        }
    }
    __syncthreads();

    // gconv2 gather (4 ch/thread): u[2 x 50 x 64] at SFT (feat dead)
    for (int i = t; i < 100 * 16; i += TPB) {
        int n = i >> 4, cp = (i & 15) << 2;
        int ph = (n >= 50), ln = n - 50 * ph;
        u64 a0 = 0ull, a1 = 0ull;
        {
            int e1 = sstart[ph * 51 + ln + 1];
            for (int e = sstart[ph * 51 + ln]; e < e1; ++e) {
                int s = srts[ph * EPN + e];
                u64 ww; DUP2(ww, sm[SRTW + ph * EPN + e]);
                ulonglong2 x = *(const ulonglong2*)(sm + ST + (ph * 64 + s) * C2 + cp);
                FMA2(a0, x.x, ww, a0);
                FMA2(a1, x.y, ww, a1);
            }
            u64 rr; DUP2(rr, sm[SRSI + ph * NPN + ln]);
            MUL2(a0, a0, rr);
            MUL2(a1, a1, rr);
        }
        ulonglong2 o; o.x = a0; o.y = a1;
        *(ulonglong2*)(sm + SFT + ph * 3200 + ln * C2 + cp) = o;
    }
    __syncthreads();

    // ---- layer-2 norm: 128 (patch, channel) threads ----
    if (t < 2 * C2) {
        int ph = t >> 6, c = t & 63;
        const float* row = sm + SFT + ph * 3200 + c;
        float s = 0.f, s2 = 0.f;
        for (int n = 0; n < NPN; n++) {
            float v = row[n * C2];
            s += v; s2 = fmaf(v, v, s2);
        }
        float mu = s * (1.f / NPN), var = s2 * (1.f / NPN) - mu * mu;
        float sc = g2[c] * rsqrtf(var + EPSV);
        sm[SGA + ph * HE + c] = sc;
        sm[SGB + ph * HE + c] = b2[c] - mu * sc;
    }
    __syncthreads();
    if (t < 2 * C2) {  // apply + lrelu + r2
        int ph = t >> 6, c = t & 63;
        float sc = sm[SGA + ph * HE + c], sh = sm[SGB + ph * HE + c];
        float* row = sm + SFT + ph * 3200 + c;
        float s = 0.f;
        for (int n = 0; n < NPN; n++) {
            float v = fmaf(row[n * C2], sc, sh);
            v = v >= 0.f ? v : SLOPE * v;
            row[n * C2] = v;
            s += v;
        }
        sm[SRV + ph * 384 + 320 + c] = s * (1.f / NPN);
    }
    __syncthreads();

    // readout: emb_ph = rvec_ph[384] @ We[384x128]; 4 k-groups of 96 per patch
    {
        int ph = t >> 8, tt = t & 255;
        int jp = (tt & 63) * 2, hf = tt >> 6;
        int k0 = hf * 96;
        const float* rv = sm + SRV + ph * 384;
        u64 a = 0ull;
        for (int k = k0; k < k0 + 96; k++) {
            u64 d; DUP2(d, rv[k]);
            u64 w = __ldg((const u64*)(We + k * RD + jp));
            FMA2(a, d, w, a);
        }
        *(u64*)(sm + ST + ph * 512 + hf * 128 + jp) = a;
    }
    __syncthreads();
    if (t < 128) {  // reduce 4 partials -> emb pair
        int ph = t >> 6, pr = t & 63;
        u64 a = *(const u64*)(sm + ST + ph * 512 + pr * 2);
        #pragma unroll
        for (int h = 1; h < 4; h++) {
            u64 b_ = *(const u64*)(sm + ST + ph * 512 + h * 128 + pr * 2);
            ADD2(a, a, b_);
        }
        *(u64*)(sm + SRED + ph * RD + pr * 2) = a;
    }
    __syncthreads();
    if (t < 64) {  // instance-norm stats: warp 0 -> patch A, warp 1 -> patch B
        int ph = t >> 5, lane = t & 31;
        float s = 0.f, s2 = 0.f;
        #pragma unroll
        for (int i = 0; i < 4; i++) {
            float v = sm[SRED + ph * RD + lane * 4 + i];
            s += v; s2 = fmaf(v, v, s2);
        }
        #pragma unroll
        for (int o = 16; o; o >>= 1) {
            s  += __shfl_down_sync(0xffffffffu, s,  o);
            s2 += __shfl_down_sync(0xffffffffu, s2, o);
        }
        if (lane == 0) {
            float mu = s * (1.f / RD), var = s2 * (1.f / RD) - mu * mu;
            sm[SGA + ph * 2] = mu;
            sm[SGA + ph * 2 + 1] = rsqrtf(var + EPSV);
        }
    }
    __syncthreads();
    if (t < 2 * RD) {
        int ph = t >> 7, c = t & 127;
        float y = (sm[SRED + ph * RD + c] - sm[SGA + ph * 2]) * sm[SGA + ph * 2 + 1];
        y = y >= 0.f ? y : SLOPE * y;
        gEmb[(long long)(p0 + ph) * RD + c] = y;
    }
}

// =====================================================================
// Mesh stage: CSR gather, f32x2 math, float4 loads (unchanged)
// =====================================================================
__global__ void init_zero() {
    int i = blockIdx.x * 256 + threadIdx.x;
    if (i < P) { gCntOut[i] = 0; gCntIn[i] = 0; gFill[i] = 0; }
    if (i < 2 * HM) { gSums[i] = 0.0; gSums2[i] = 0.0; gRoSum[i] = 0.0; }
}

__global__ void mesh_deg(const int* __restrict__ src, const int* __restrict__ dst) {
    int e = blockIdx.x * 256 + threadIdx.x;
    if (e < EM) { atomicAdd(&gCntOut[src[e]], 1); atomicAdd(&gCntIn[dst[e]], 1); }
}

__global__ void mesh_rs() {
    int i = blockIdx.x * 256 + threadIdx.x;
    if (i < P) {
        gRsOut[i] = rsqrtf((float)(gCntOut[i] > 0 ? gCntOut[i] : 1));
        gRsIn[i]  = rsqrtf((float)(gCntIn[i]  > 0 ? gCntIn[i]  : 1));
    }
}

__global__ void mesh_scan() {
    __shared__ int part[256];
    int t = threadIdx.x;
    const int CH = (P + 255) / 256;
    int base = t * CH, s = 0;
    for (int i = 0; i < CH; i++) { int idx = base + i; if (idx < P) s += gCntIn[idx]; }
    part[t] = s; __syncthreads();
    for (int off = 1; off < 256; off <<= 1) {
        int v = (t >= off) ? part[t - off] : 0;
        __syncthreads();
        part[t] += v;
        __syncthreads();
    }
    int run = (t == 0) ? 0 : part[t - 1];
    for (int i = 0; i < CH; i++) {
        int idx = base + i;
        if (idx < P) { gOffs[idx] = run; run += gCntIn[idx]; }
    }
    if (t == 255) gOffs[P] = run;
}

__global__ void mesh_sort(const int* __restrict__ src, const int* __restrict__ dst,
                          const float* __restrict__ ew) {
    int e = blockIdx.x * 256 + threadIdx.x;
    if (e < EM) {
        int d = dst[e], s = src[e];
        int pos = gOffs[d] + atomicAdd(&gFill[d], 1);
        gSrtSrc[pos] = s;
        gSrtW[pos] = ew[e] * gRsOut[s];
    }
}

__global__ void mesh_gather128(const float* __restrict__ X, float* __restrict__ Y) {
    int n = blockIdx.x * 8 + (threadIdx.x >> 5);
    int cp = (threadIdx.x & 31) * 4;
    int e1 = gOffs[n + 1];
    u64 a0 = 0ull, a1 = 0ull;
    for (int e = gOffs[n]; e < e1; ++e) {
        u64 ww; DUP2(ww, gSrtW[e]);
        ulonglong2 x = __ldg((const ulonglong2*)(X + (long long)gSrtSrc[e] * 128 + cp));
        FMA2(a0, x.x, ww, a0);
        FMA2(a1, x.y, ww, a1);
    }
    u64 rr; DUP2(rr, gRsIn[n]);
    MUL2(a0, a0, rr); MUL2(a1, a1, rr);
    ulonglong2 o; o.x = a0; o.y = a1;
    *(ulonglong2*)(Y + (long long)n * 128 + cp) = o;
}

__global__ void mesh_gather256(const float* __restrict__ X, float* __restrict__ Y) {
    int n = blockIdx.x * 4 + (threadIdx.x >> 6);
    int cp = (threadIdx.x & 63) * 4;
    int e1 = gOffs[n + 1];
    u64 a0 = 0ull, a1 = 0ull;
    for (int e = gOffs[n]; e < e1; ++e) {
        u64 ww; DUP2(ww, gSrtW[e]);
        ulonglong2 x = __ldg((const ulonglong2*)(X + (long long)gSrtSrc[e] * 256 + cp));
        FMA2(a0, x.x, ww, a0);
        FMA2(a1, x.y, ww, a1);
    }
    u64 rr; DUP2(rr, gRsIn[n]);
    MUL2(a0, a0, rr); MUL2(a1, a1, rr);
    ulonglong2 o; o.x = a0; o.y = a1;
    *(ulonglong2*)(Y + (long long)n * 256 + cp) = o;
}

template <int K>
__global__ void __launch_bounds__(256) mesh_gemm(const float* __restrict__ X,
                                                 const float* __restrict__ W,
                                                 float* __restrict__ Y) {
    __shared__ float xs[16 * K];
    int r0 = blockIdx.x * 16;
    int t = threadIdx.x;
    for (int i = t; i < 16 * K; i += 256)
        xs[i] = X[(long long)r0 * K + i];
    __syncthreads();
    int c0 = (t & 63) * 4, tr = t >> 6;
    u64 a0[4], a1[4];
    #pragma unroll
    for (int j = 0; j < 4; j++) { a0[j] = 0ull; a1[j] = 0ull; }
    for (int k4 = 0; k4 < K / 4; k4++) {
        int k = k4 * 4;
        ulonglong2 w0 = __ldg((const ulonglong2*)(W + (k + 0) * HM + c0));
        ulonglong2 w1 = __ldg((const ulonglong2*)(W + (k + 1) * HM + c0));
        ulonglong2 w2 = __ldg((const ulonglong2*)(W + (k + 2) * HM + c0));
        ulonglong2 w3 = __ldg((const ulonglong2*)(W + (k + 3) * HM + c0));
        #pragma unroll
        for (int j = 0; j < 4; j++) {
            float4 x = *(const float4*)(xs + (tr + 4 * j) * K + k);
            u64 d;
            DUP2(d, x.x); FMA2(a0[j], d, w0.x, a0[j]); FMA2(a1[j], d, w0.y, a1[j]);
            DUP2(d, x.y); FMA2(a0[j], d, w1.x, a0[j]); FMA2(a1[j], d, w1.y, a1[j]);
            DUP2(d, x.z); FMA2(a0[j], d, w2.x, a0[j]); FMA2(a1[j], d, w2.y, a1[j]);
            DUP2(d, x.w); FMA2(a0[j], d, w3.x, a0[j]); FMA2(a1[j], d, w3.y, a1[j]);
        }
    }
    #pragma unroll
    for (int j = 0; j < 4; j++) {
        ulonglong2 o; o.x = a0[j]; o.y = a1[j];
        *(ulonglong2*)(Y + (long long)(r0 + tr + 4 * j) * HM + c0) = o;
    }
}

__global__ void mesh_stats(const float* __restrict__ Y, int off) {
    int c = threadIdx.x;
    int r0 = blockIdx.x * 50;
    float s = 0.f, s2 = 0.f;
    for (int i = 0; i < 50; i++) {
        float v = Y[(long long)(r0 + i) * HM + c];
        s += v; s2 = fmaf(v, v, s2);
    }
    atomicAdd(&gSums[off + c], (double)s);
    atomicAdd(&gSums2[off + c], (double)s2);
}

__global__ void mesh_finalize(const float* __restrict__ g, const float* __restrict__ b, int off) {
    int c = threadIdx.x;
    double mu = gSums[off + c] / P;
    double var = gSums2[off + c] / P - mu * mu;
    float sc = g[c] * rsqrtf((float)var + EPSV);
    gScale[off + c] = sc;
    gShift[off + c] = b[c] - (float)mu * sc;
}

__global__ void mesh_apply(float* __restrict__ Y, int off) {
    int c = threadIdx.x;
    int r0 = blockIdx.x * 50;
    float sc = gScale[off + c], sh = gShift[off + c];
    float s = 0.f;
    for (int i = 0; i < 50; i++) {
        long long idx = (long long)(r0 + i) * HM + c;
        float v = fmaf(Y[idx], sc, sh);
        v = v >= 0.f ? v : SLOPE * v;
        Y[idx] = v;
        s += v;
    }
    atomicAdd(&gRoSum[off + c], (double)s);
}

__global__ void final_kernel(const float* __restrict__ Wcls, float* __restrict__ out) {
    int t = threadIdx.x;
    if (t < OUTC) {
        float a = 0.f;
        for (int k = 0; k < 2 * HM; k++)
            a = fmaf((float)(gRoSum[k] / P), __ldg(&Wcls[k * OUTC + t]), a);
        out[t] = a;
    }
}

// =====================================================================
extern "C" void kernel_launch(void* const* d_in, const int* in_sizes, int n_in,
                              void* d_out, int out_size) {
    const float* patch_feats = (const float*)d_in[0];
    const int*   patch_src   = (const int*)d_in[1];
    const int*   patch_dst   = (const int*)d_in[2];
    const float* patch_ew    = (const float*)d_in[3];
    const int*   mesh_src    = (const int*)d_in[4];
    const int*   mesh_dst    = (const int*)d_in[5];
    const float* mesh_ew     = (const float*)d_in[6];
    const float* W1  = (const float*)d_in[7];
    const float* g1  = (const float*)d_in[8];
    const float* b1  = (const float*)d_in[9];
    const float* W2  = (const float*)d_in[10];
    const float* g2  = (const float*)d_in[11];
    const float* b2  = (const float*)d_in[12];
    const float* We  = (const float*)d_in[13];
    const float* Wc1 = (const float*)d_in[14];
    const float* g3  = (const float*)d_in[15];
    const float* b3  = (const float*)d_in[16];
    const float* Wc2 = (const float*)d_in[17];
    const float* g4  = (const float*)d_in[18];
    const float* b4  = (const float*)d_in[19];
    const float* Wcls = (const float*)d_in[20];
    float* out = (float*)d_out;

    cudaFuncSetAttribute(patch_kernel, cudaFuncAttributeMaxDynamicSharedMemorySize, SMEM_PATCH);

    void *pEmb, *pAgg1, *pAgg2, *pH, *pH2;
    cudaGetSymbolAddress(&pEmb,  gEmb);
    cudaGetSymbolAddress(&pAgg1, gAgg1);
    cudaGetSymbolAddress(&pAgg2, gAgg2);
    cudaGetSymbolAddress(&pH,    gH);
    cudaGetSymbolAddress(&pH2,   gH2);

    // keep patch_kernel as 4th launch so ncu's window lands on it
    init_zero<<<(P + 255) / 256, 256>>>();
    mesh_deg<<<(EM + 255) / 256, 256>>>(mesh_src, mesh_dst);
    mesh_rs<<<(P + 255) / 256, 256>>>();

    patch_kernel<<<P / 2, TPB, SMEM_PATCH>>>(patch_feats, patch_src, patch_dst, patch_ew,
                                             W1, g1, b1, W2, g2, b2, We);

    mesh_scan<<<1, 256>>>();
    mesh_sort<<<(EM + 255) / 256, 256>>>(mesh_src, mesh_dst, mesh_ew);

    // mesh conv1
    mesh_gather128<<<P / 8, 256>>>((const float*)pEmb, (float*)pAgg1);
    mesh_gemm<RD><<<P / 16, 256>>>((const float*)pAgg1, Wc1, (float*)pH);
    mesh_stats<<<P / 50, 256>>>((const float*)pH, 0);
    mesh_finalize<<<1, 256>>>(g3, b3, 0);
    mesh_apply<<<P / 50, 256>>>((float*)pH, 0);

    // mesh conv2
    mesh_gather256<<<P / 4, 256>>>((const float*)pH, (float*)pAgg2);
    mesh_gemm<HM><<<P / 16, 256>>>((const float*)pAgg2, Wc2, (float*)pH2);
    mesh_stats<<<P / 50, 256>>>((const float*)pH2, HM);
    mesh_finalize<<<1, 256>>>(g4, b4, HM);
    mesh_apply<<<P / 50, 256>>>((float*)pH2, HM);

    final_kernel<<<1, 32>>>(Wcls, out);
}

// round 17
// speedup vs baseline: 1.0505x; 1.0505x over previous
#include <cuda_runtime.h>

// ---------------- problem constants ----------------
constexpr int P    = 10000;
constexpr int NPN  = 50;
constexpr int EPN  = 200;
constexpr int IN   = 64;
constexpr int HE   = 256;
constexpr int C2   = 64;
constexpr int RD   = 128;
constexpr int HM   = 256;
constexpr int OUTC = 16;
constexpr int EM   = 160000;
constexpr float EPSV  = 1e-5f;
constexpr float SLOPE = 0.01f;
constexpr int TPB  = 512;   // patch kernel threads

// ---------------- packed fp32x2 helpers (sm_103a) ----------------
typedef unsigned long long u64;
#define FMA2(d, a, b, c) asm("fma.rn.f32x2 %0, %1, %2, %3;" : "=l"(d) : "l"(a), "l"(b), "l"(c))
#define MUL2(d, a, b)    asm("mul.rn.f32x2 %0, %1, %2;"     : "=l"(d) : "l"(a), "l"(b))
#define ADD2(d, a, b)    asm("add.rn.f32x2 %0, %1, %2;"     : "=l"(d) : "l"(a), "l"(b))
#define DUP2(d, x)       asm("mov.b64 %0, {%1, %1};"        : "=l"(d) : "r"(__float_as_uint(x)))

// ---------------- device scratch ----------------
__device__ float  gEmb[P * RD];
__device__ int    gCntOut[P], gCntIn[P], gFill[P];
__device__ int    gOffs[P + 1];
__device__ float  gRsOut[P], gRsIn[P];
__device__ int    gSrtSrc[EM];
__device__ float  gSrtW[EM];
__device__ float  gAgg1[P * RD];
__device__ float  gAgg2[P * HM];
__device__ float  gH[P * HM];
__device__ float  gH2[P * HM];
__device__ double gSums[2 * HM], gSums2[2 * HM], gRoSum[2 * HM];
__device__ float  gScale[2 * HM], gShift[2 * HM];

// ---------------- patch kernel smem layout (float indices) ----------------
constexpr int H1S  = 264;              // padded h1 row stride (16B-mult)
constexpr int SH1  = 0;                // h1 [64 x 264] (rows 52..63 zero)
constexpr int ST   = 64 * H1S;         // t1 [56x64] / t2 [64x64] / scratch
constexpr int SFT  = ST + 64 * 64;     // feat [50x64] then u [52x64]
constexpr int SEW  = SFT + 3328;       // raw edge weights [200]
constexpr int SRTW = SEW + EPN;        // sorted weights [200]
constexpr int SRSO = SRTW + EPN;       // rsqrt deg_out [50]
constexpr int SRSI = SRSO + NPN;       // rsqrt deg_in  [50]
constexpr int SR0  = SRSI + NPN;       // r0[64] r1[256] r2[64] contiguous
constexpr int SR1  = SR0 + IN;
constexpr int SR2  = SR1 + HE;
constexpr int SGA  = SR2 + C2;         // scale [256]
constexpr int SGB  = SGA + HE;         // shift [256]
constexpr int SRED = SGB + HE;         // emb [256]
constexpr int SINT = SRED + HE;
constexpr int NI_SSRC = 0, NI_SDST = EPN, NI_SRTS = 2 * EPN;
constexpr int NI_START = 3 * EPN;      // [51]
constexpr int NI_FILL  = NI_START + NPN + 1;
constexpr int NI_CIN   = NI_FILL + NPN;
constexpr int NI_COUT  = NI_CIN + NPN;
constexpr int NINTS    = NI_COUT + NPN;
constexpr int SMEM_PATCH = (SINT + NINTS) * 4;   // ~107 KB -> 2 CTAs/SM

// =====================================================================
// Patch embedder: one CTA per patch, 512 threads, f32x2 math. (R11)
// =====================================================================
__global__ void __launch_bounds__(TPB, 2) patch_kernel(
    const float* __restrict__ feats, const int* __restrict__ srcs,
    const int* __restrict__ dsts, const float* __restrict__ ews,
    const float* __restrict__ W1, const float* __restrict__ g1,
    const float* __restrict__ b1, const float* __restrict__ W2,
    const float* __restrict__ g2, const float* __restrict__ b2,
    const float* __restrict__ We)
{
    extern __shared__ float sm[];
    int* smi    = (int*)(sm + SINT);
    int* ssrc   = smi + NI_SSRC;
    int* sdst   = smi + NI_SDST;
    int* srts   = smi + NI_SRTS;
    int* sstart = smi + NI_START;
    int* sfill  = smi + NI_FILL;
    int* scin   = smi + NI_CIN;
    int* scout  = smi + NI_COUT;
    const int p = blockIdx.x, t = threadIdx.x;

    for (int i = t; i < EPN; i += TPB) {
        ssrc[i] = srcs[p * EPN + i];
        sdst[i] = dsts[p * EPN + i];
        sm[SEW + i] = ews[p * EPN + i];
    }
    {
        const float4* f4 = (const float4*)(feats + (long long)p * NPN * IN);
        float4* s4 = (float4*)(sm + SFT);
        for (int i = t; i < NPN * IN / 4; i += TPB) s4[i] = f4[i];
    }
    for (int i = t; i < NPN; i += TPB) { scin[i] = 0; scout[i] = 0; sfill[i] = 0; }
    // zero h1 rows 52..63 (GEMM2 reads a full 64-row tile)
    for (int i = t; i < 12 * H1S; i += TPB) sm[SH1 + 52 * H1S + i] = 0.f;
    __syncthreads();

    if (t < EPN) { atomicAdd(&scout[ssrc[t]], 1); atomicAdd(&scin[sdst[t]], 1); }
    __syncthreads();
    if (t < NPN) {
        sm[SRSO + t] = rsqrtf((float)(scout[t] > 0 ? scout[t] : 1));
        sm[SRSI + t] = rsqrtf((float)(scin[t]  > 0 ? scin[t]  : 1));
    }
    if (t == TPB - 1) {  // serial 50-elem scan
        int s = 0;
        for (int n = 0; n < NPN; n++) { sstart[n] = s; s += scin[n]; }
        sstart[NPN] = s;
    }
    if (t < IN) {  // r0 = feat.mean(0)
        float s = 0.f;
        for (int n = 0; n < NPN; n++) s += sm[SFT + n * IN + t];
        sm[SR0 + t] = s * (1.f / NPN);
    }
    __syncthreads();

    if (t < EPN) {  // counting sort by dst; fold rsqrt(deg_out[src]) into w
        int d = sdst[t];
        int pos = sstart[d] + atomicAdd(&sfill[d], 1);
        srts[pos] = ssrc[t];
        sm[SRTW + pos] = sm[SEW + t] * sm[SRSO + ssrc[t]];
    }
    __syncthreads();

    // gconv1 gather (4 ch/thread): t1[56 x 64], rows >= 50 zero
    for (int i = t; i < 56 * 16; i += TPB) {
        int n = i >> 4, cp = (i & 15) << 2;
        u64 a0 = 0ull, a1 = 0ull;
        if (n < NPN) {
            int e1 = sstart[n + 1];
            for (int e = sstart[n]; e < e1; ++e) {
                int s = srts[e];
                u64 ww; DUP2(ww, sm[SRTW + e]);
                ulonglong2 x = *(const ulonglong2*)(sm + SFT + s * IN + cp);
                FMA2(a0, x.x, ww, a0);
                FMA2(a1, x.y, ww, a1);
            }
            u64 rr; DUP2(rr, sm[SRSI + n]);
            MUL2(a0, a0, rr);
            MUL2(a1, a1, rr);
        }
        ulonglong2 o; o.x = a0; o.y = a1;
        *(ulonglong2*)(sm + ST + n * IN + cp) = o;
    }
    __syncthreads();

    // GEMM1: h1[56 x 256(pad 264)] = t1[56x64] @ W1[64x256]
    {
        int c0 = (t & 63) * 4, rg = t >> 6;
        u64 a0[7], a1[7];
        #pragma unroll
        for (int j = 0; j < 7; j++) { a0[j] = 0ull; a1[j] = 0ull; }
        for (int k4 = 0; k4 < IN / 4; k4++) {
            int k = k4 * 4;
            ulonglong2 w0 = __ldg((const ulonglong2*)(W1 + (k + 0) * HE + c0));
            ulonglong2 w1 = __ldg((const ulonglong2*)(W1 + (k + 1) * HE + c0));
            ulonglong2 w2 = __ldg((const ulonglong2*)(W1 + (k + 2) * HE + c0));
            ulonglong2 w3 = __ldg((const ulonglong2*)(W1 + (k + 3) * HE + c0));
            #pragma unroll
            for (int j = 0; j < 7; j++) {
                float4 x = *(const float4*)(sm + ST + (rg + j * 8) * IN + k);
                u64 d;
                DUP2(d, x.x); FMA2(a0[j], d, w0.x, a0[j]); FMA2(a1[j], d, w0.y, a1[j]);
                DUP2(d, x.y); FMA2(a0[j], d, w1.x, a0[j]); FMA2(a1[j], d, w1.y, a1[j]);
                DUP2(d, x.z); FMA2(a0[j], d, w2.x, a0[j]); FMA2(a1[j], d, w2.y, a1[j]);
                DUP2(d, x.w); FMA2(a0[j], d, w3.x, a0[j]); FMA2(a1[j], d, w3.y, a1[j]);
            }
        }
        #pragma unroll
        for (int j = 0; j < 7; j++) {
            ulonglong2 o; o.x = a0[j]; o.y = a1[j];
            *(ulonglong2*)(sm + SH1 + (rg + j * 8) * H1S + c0) = o;
        }
    }
    __syncthreads();

    // ---- layer-1 norm: split stats across 512 threads (ST scratch) ----
    {
        int c = t & 255, n0 = (t >> 8) * 25;
        float s = 0.f, s2 = 0.f;
        for (int n = n0; n < n0 + 25; n++) {
            float v = sm[SH1 + n * H1S + c];
            s += v; s2 = fmaf(v, v, s2);
        }
        sm[ST + t] = s; sm[ST + 512 + t] = s2;
    }
    __syncthreads();
    if (t < HE) {
        float s  = sm[ST + t] + sm[ST + 256 + t];
        float s2 = sm[ST + 512 + t] + sm[ST + 768 + t];
        float mu = s * (1.f / NPN), var = s2 * (1.f / NPN) - mu * mu;
        float sc = g1[t] * rsqrtf(var + EPSV);
        sm[SGA + t] = sc; sm[SGB + t] = b1[t] - mu * sc;
    }
    __syncthreads();
    {   // apply + lrelu + r1 partials in one pass
        int c = t & 255, n0 = (t >> 8) * 25;
        float sc = sm[SGA + c], sh = sm[SGB + c];
        float s = 0.f;
        for (int n = n0; n < n0 + 25; n++) {
            float v = fmaf(sm[SH1 + n * H1S + c], sc, sh);
            v = v >= 0.f ? v : SLOPE * v;
            sm[SH1 + n * H1S + c] = v;
            s += v;
        }
        sm[ST + t] = s;
    }
    __syncthreads();
    if (t < HE) sm[SR1 + t] = (sm[ST + t] + sm[ST + 256 + t]) * (1.f / NPN);
    __syncthreads();

    // GEMM2: t2[64x64] = h1[64x264] @ W2[256x64]
    // 16 colg x 8 rows/thread x 4-way lane-K-split, interleaved comb
    // k = 16*i4 + 4*ks: compile-time strides; ks lanes hit +0/+16/+32/+48B.
    {
        int lane = t & 31, w = t >> 5;
        int ks   = (lane >> 3) & 3;
        int c0   = ((lane & 7) | ((w & 1) << 3)) * 4;
        int rg   = w >> 1;                          // 0..7
        u64 a0[8], a1[8];
        #pragma unroll
        for (int j = 0; j < 8; j++) { a0[j] = 0ull; a1[j] = 0ull; }
        const float* px = sm + SH1 + rg * H1S + ks * 4;
        const float* pw = W2 + (ks * 4) * C2 + c0;
        #pragma unroll
        for (int i4 = 0; i4 < 16; i4++) {
            ulonglong2 w0 = __ldg((const ulonglong2*)(pw));
            ulonglong2 w1 = __ldg((const ulonglong2*)(pw + C2));
            ulonglong2 w2 = __ldg((const ulonglong2*)(pw + 2 * C2));
            ulonglong2 w3 = __ldg((const ulonglong2*)(pw + 3 * C2));
            #pragma unroll
            for (int j = 0; j < 8; j++) {
                float4 x = *(const float4*)(px + 8 * j * H1S);
                u64 d;
                DUP2(d, x.x); FMA2(a0[j], d, w0.x, a0[j]); FMA2(a1[j], d, w0.y, a1[j]);
                DUP2(d, x.y); FMA2(a0[j], d, w1.x, a0[j]); FMA2(a1[j], d, w1.y, a1[j]);
                DUP2(d, x.z); FMA2(a0[j], d, w2.x, a0[j]); FMA2(a1[j], d, w2.y, a1[j]);
                DUP2(d, x.w); FMA2(a0[j], d, w3.x, a0[j]); FMA2(a1[j], d, w3.y, a1[j]);
            }
            px += 16;
            pw += 16 * C2;
        }
        #pragma unroll
        for (int j = 0; j < 8; j++) {
            float2 v0 = *(float2*)&a0[j];
            float2 v1 = *(float2*)&a1[j];
            v0.x += __shfl_xor_sync(0xffffffffu, v0.x, 8);
            v0.y += __shfl_xor_sync(0xffffffffu, v0.y, 8);
            v1.x += __shfl_xor_sync(0xffffffffu, v1.x, 8);
            v1.y += __shfl_xor_sync(0xffffffffu, v1.y, 8);
            v0.x += __shfl_xor_sync(0xffffffffu, v0.x, 16);
            v0.y += __shfl_xor_sync(0xffffffffu, v0.y, 16);
            v1.x += __shfl_xor_sync(0xffffffffu, v1.x, 16);
            v1.y += __shfl_xor_sync(0xffffffffu, v1.y, 16);
            if (ks == 0) {
                float4 o = make_float4(v0.x, v0.y, v1.x, v1.y);
                *(float4*)(sm + ST + (rg + 8 * j) * C2 + c0) = o;
            }
        }
    }
    __syncthreads();

    // gconv2 gather (4 ch/thread) on 64 channels: u[52x64] at SFT
    for (int i = t; i < 52 * 16; i += TPB) {
        int n = i >> 4, cp = (i & 15) << 2;
        u64 a0 = 0ull, a1 = 0ull;
        if (n < NPN) {
            int e1 = sstart[n + 1];
            for (int e = sstart[n]; e < e1; ++e) {
                int s = srts[e];
                u64 ww; DUP2(ww, sm[SRTW + e]);
                ulonglong2 x = *(const ulonglong2*)(sm + ST + s * C2 + cp);
                FMA2(a0, x.x, ww, a0);
                FMA2(a1, x.y, ww, a1);
            }
            u64 rr; DUP2(rr, sm[SRSI + n]);
            MUL2(a0, a0, rr);
            MUL2(a1, a1, rr);
        }
        ulonglong2 o; o.x = a0; o.y = a1;
        *(ulonglong2*)(sm + SFT + n * C2 + cp) = o;
    }
    __syncthreads();

    // ---- layer-2 norm: split stats (8 groups of strided rows, ST dead) ----
    {
        int c = t & 63, q = t >> 6;
        float s = 0.f, s2 = 0.f;
        for (int n = q; n < NPN; n += 8) {
            float v = sm[SFT + n * C2 + c];
            s += v; s2 = fmaf(v, v, s2);
        }
        sm[ST + t] = s; sm[ST + 512 + t] = s2;
    }
    __syncthreads();
    if (t < C2) {
        float s = 0.f, s2 = 0.f;
        #pragma unroll
        for (int q = 0; q < 8; q++) { s += sm[ST + q * 64 + t]; s2 += sm[ST + 512 + q * 64 + t]; }
        float mu = s * (1.f / NPN), var = s2 * (1.f / NPN) - mu * mu;
        float sc = g2[t] * rsqrtf(var + EPSV);
        sm[SGA + t] = sc; sm[SGB + t] = b2[t] - mu * sc;
    }
    __syncthreads();
    {   // apply + lrelu + r2 partials
        int c = t & 63, q = t >> 6;
        float sc = sm[SGA + c], sh = sm[SGB + c];
        float s = 0.f;
        for (int n = q; n < NPN; n += 8) {
            float v = fmaf(sm[SFT + n * C2 + c], sc, sh);
            v = v >= 0.f ? v : SLOPE * v;
            sm[SFT + n * C2 + c] = v;
            s += v;
        }
        sm[ST + t] = s;
    }
    __syncthreads();
    if (t < C2) {
        float s = 0.f;
        #pragma unroll
        for (int q = 0; q < 8; q++) s += sm[ST + q * 64 + t];
        sm[SR2 + t] = s * (1.f / NPN);
    }
    __syncthreads();

    // emb = concat(r0,r1,r2)[384] @ We[384x128]  (8 k-groups of 48)
    {
        int jp = (t & 63) * 2, hf = t >> 6;
        int k0 = hf * 48;
        u64 a = 0ull;
        for (int k = k0; k < k0 + 48; k++) {
            u64 d; DUP2(d, sm[SR0 + k]);
            u64 w = __ldg((const u64*)(We + k * RD + jp));
            FMA2(a, d, w, a);
        }
        *(u64*)(sm + ST + hf * 128 + jp) = a;
    }
    __syncthreads();
    if (t < 64) {  // reduce 8 partials -> emb pair at SRED
        u64 a = *(const u64*)(sm + ST + t * 2);
        #pragma unroll
        for (int h = 1; h < 8; h++) {
            u64 b_ = *(const u64*)(sm + ST + h * 128 + t * 2);
            ADD2(a, a, b_);
        }
        *(u64*)(sm + SRED + t * 2) = a;
    }
    __syncthreads();
    if (t < 32) {  // instance-norm stats over 128 channels (warp reduce)
        float s = 0.f, s2 = 0.f;
        #pragma unroll
        for (int i = 0; i < 4; i++) { float v = sm[SRED + t * 4 + i]; s += v; s2 = fmaf(v, v, s2); }
        #pragma unroll
        for (int o = 16; o; o >>= 1) {
            s  += __shfl_down_sync(0xffffffffu, s,  o);
            s2 += __shfl_down_sync(0xffffffffu, s2, o);
        }
        if (t == 0) {
            float mu = s * (1.f / RD), var = s2 * (1.f / RD) - mu * mu;
            sm[SGA] = mu; sm[SGA + 1] = rsqrtf(var + EPSV);
        }
    }
    __syncthreads();
    if (t < RD) {
        float y = (sm[SRED + t] - sm[SGA]) * sm[SGA + 1];
        y = y >= 0.f ? y : SLOPE * y;
        gEmb[p * RD + t] = y;
    }
}

// =====================================================================
// Mesh stage: CSR gather, f32x2 math; stats fused into GEMM epilogue.
// =====================================================================
__global__ void init_zero() {
    int i = blockIdx.x * 256 + threadIdx.x;
    if (i < P) { gCntOut[i] = 0; gCntIn[i] = 0; gFill[i] = 0; }
    if (i < 2 * HM) { gSums[i] = 0.0; gSums2[i] = 0.0; gRoSum[i] = 0.0; }
}

__global__ void mesh_deg(const int* __restrict__ src, const int* __restrict__ dst) {
    int e = blockIdx.x * 256 + threadIdx.x;
    if (e < EM) { atomicAdd(&gCntOut[src[e]], 1); atomicAdd(&gCntIn[dst[e]], 1); }
}

__global__ void mesh_rs() {
    int i = blockIdx.x * 256 + threadIdx.x;
    if (i < P) {
        gRsOut[i] = rsqrtf((float)(gCntOut[i] > 0 ? gCntOut[i] : 1));
        gRsIn[i]  = rsqrtf((float)(gCntIn[i]  > 0 ? gCntIn[i]  : 1));
    }
}

__global__ void mesh_scan() {
    __shared__ int part[256];
    int t = threadIdx.x;
    const int CH = (P + 255) / 256;
    int base = t * CH, s = 0;
    for (int i = 0; i < CH; i++) { int idx = base + i; if (idx < P) s += gCntIn[idx]; }
    part[t] = s; __syncthreads();
    for (int off = 1; off < 256; off <<= 1) {
        int v = (t >= off) ? part[t - off] : 0;
        __syncthreads();
        part[t] += v;
        __syncthreads();
    }
    int run = (t == 0) ? 0 : part[t - 1];
    for (int i = 0; i < CH; i++) {
        int idx = base + i;
        if (idx < P) { gOffs[idx] = run; run += gCntIn[idx]; }
    }
    if (t == 255) gOffs[P] = run;
}

__global__ void mesh_sort(const int* __restrict__ src, const int* __restrict__ dst,
                          const float* __restrict__ ew) {
    int e = blockIdx.x * 256 + threadIdx.x;
    if (e < EM) {
        int d = dst[e], s = src[e];
        int pos = gOffs[d] + atomicAdd(&gFill[d], 1);
        gSrtSrc[pos] = s;
        gSrtW[pos] = ew[e] * gRsOut[s];
    }
}

__global__ void mesh_gather128(const float* __restrict__ X, float* __restrict__ Y) {
    int n = blockIdx.x * 8 + (threadIdx.x >> 5);
    int cp = (threadIdx.x & 31) * 4;
    int e1 = gOffs[n + 1];
    u64 a0 = 0ull, a1 = 0ull;
    for (int e = gOffs[n]; e < e1; ++e) {
        u64 ww; DUP2(ww, gSrtW[e]);
        ulonglong2 x = __ldg((const ulonglong2*)(X + (long long)gSrtSrc[e] * 128 + cp));
        FMA2(a0, x.x, ww, a0);
        FMA2(a1, x.y, ww, a1);
    }
    u64 rr; DUP2(rr, gRsIn[n]);
    MUL2(a0, a0, rr); MUL2(a1, a1, rr);
    ulonglong2 o; o.x = a0; o.y = a1;
    *(ulonglong2*)(Y + (long long)n * 128 + cp) = o;
}

__global__ void mesh_gather256(const float* __restrict__ X, float* __restrict__ Y) {
    int n = blockIdx.x * 4 + (threadIdx.x >> 6);
    int cp = (threadIdx.x & 63) * 4;
    int e1 = gOffs[n + 1];
    u64 a0 = 0ull, a1 = 0ull;
    for (int e = gOffs[n]; e < e1; ++e) {
        u64 ww; DUP2(ww, gSrtW[e]);
        ulonglong2 x = __ldg((const ulonglong2*)(X + (long long)gSrtSrc[e] * 256 + cp));
        FMA2(a0, x.x, ww, a0);
        FMA2(a1, x.y, ww, a1);
    }
    u64 rr; DUP2(rr, gRsIn[n]);
    MUL2(a0, a0, rr); MUL2(a1, a1, rr);
    ulonglong2 o; o.x = a0; o.y = a1;
    *(ulonglong2*)(Y + (long long)n * 256 + cp) = o;
}

// Y[P x 256] = X[P x K] @ W[K x 256]; per-block column sum/sumsq fused
// into the epilogue (replaces the separate mesh_stats kernel).
template <int K>
__global__ void __launch_bounds__(256) mesh_gemm(const float* __restrict__ X,
                                                 const float* __restrict__ W,
                                                 float* __restrict__ Y,
                                                 int soff) {
    __shared__ float xs[16 * K];   // >= 2048 floats; reused for stats reduce
    int r0 = blockIdx.x * 16;
    int t = threadIdx.x;
    for (int i = t; i < 16 * K; i += 256)
        xs[i] = X[(long long)r0 * K + i];
    __syncthreads();
    int c0 = (t & 63) * 4, tr = t >> 6;
    u64 a0[4], a1[4];
    #pragma unroll
    for (int j = 0; j < 4; j++) { a0[j] = 0ull; a1[j] = 0ull; }
    for (int k4 = 0; k4 < K / 4; k4++) {
        int k = k4 * 4;
        ulonglong2 w0 = __ldg((const ulonglong2*)(W + (k + 0) * HM + c0));
        ulonglong2 w1 = __ldg((const ulonglong2*)(W + (k + 1) * HM + c0));
        ulonglong2 w2 = __ldg((const ulonglong2*)(W + (k + 2) * HM + c0));
        ulonglong2 w3 = __ldg((const ulonglong2*)(W + (k + 3) * HM + c0));
        #pragma unroll
        for (int j = 0; j < 4; j++) {
            float4 x = *(const float4*)(xs + (tr + 4 * j) * K + k);
            u64 d;
            DUP2(d, x.x); FMA2(a0[j], d, w0.x, a0[j]); FMA2(a1[j], d, w0.y, a1[j]);
            DUP2(d, x.y); FMA2(a0[j], d, w1.x, a0[j]); FMA2(a1[j], d, w1.y, a1[j]);
            DUP2(d, x.z); FMA2(a0[j], d, w2.x, a0[j]); FMA2(a1[j], d, w2.y, a1[j]);
            DUP2(d, x.w); FMA2(a0[j], d, w3.x, a0[j]); FMA2(a1[j], d, w3.y, a1[j]);
        }
    }
    // store Y + per-thread column partials over this thread's 4 rows
    float4 ps = make_float4(0.f, 0.f, 0.f, 0.f);
    float4 pq = make_float4(0.f, 0.f, 0.f, 0.f);
    #pragma unroll
    for (int j = 0; j < 4; j++) {
        ulonglong2 o; o.x = a0[j]; o.y = a1[j];
        *(ulonglong2*)(Y + (long long)(r0 + tr + 4 * j) * HM + c0) = o;
        float2 v0 = *(float2*)&a0[j];
        float2 v1 = *(float2*)&a1[j];
        ps.x += v0.x; pq.x = fmaf(v0.x, v0.x, pq.x);
        ps.y += v0.y; pq.y = fmaf(v0.y, v0.y, pq.y);
        ps.z += v1.x; pq.z = fmaf(v1.x, v1.x, pq.z);
        ps.w += v1.y; pq.w = fmaf(v1.y, v1.y, pq.w);
    }
    __syncthreads();   // xs reads in mainloop done
    *(float4*)(xs + tr * 256 + c0) = ps;
    *(float4*)(xs + 1024 + tr * 256 + c0) = pq;
    __syncthreads();
    if (t < 256) {
        float s = xs[t] + xs[256 + t] + xs[512 + t] + xs[768 + t];
        float q = xs[1024 + t] + xs[1280 + t] + xs[1536 + t] + xs[1792 + t];
        atomicAdd(&gSums[soff + t], (double)s);
        atomicAdd(&gSums2[soff + t], (double)q);
    }
}

__global__ void mesh_finalize(const float* __restrict__ g, const float* __restrict__ b, int off) {
    int c = threadIdx.x;
    double mu = gSums[off + c] / P;
    double var = gSums2[off + c] / P - mu * mu;
    float sc = g[c] * rsqrtf((float)var + EPSV);
    gScale[off + c] = sc;
    gShift[off + c] = b[c] - (float)mu * sc;
}

__global__ void mesh_apply(float* __restrict__ Y, int off) {
    int c = threadIdx.x;
    int r0 = blockIdx.x * 50;
    float sc = gScale[off + c], sh = gShift[off + c];
    float s = 0.f;
    for (int i = 0; i < 50; i++) {
        long long idx = (long long)(r0 + i) * HM + c;
        float v = fmaf(Y[idx], sc, sh);
        v = v >= 0.f ? v : SLOPE * v;
        Y[idx] = v;
        s += v;
    }
    atomicAdd(&gRoSum[off + c], (double)s);
}

__global__ void final_kernel(const float* __restrict__ Wcls, float* __restrict__ out) {
    int t = threadIdx.x;
    if (t < OUTC) {
        float a = 0.f;
        for (int k = 0; k < 2 * HM; k++)
            a = fmaf((float)(gRoSum[k] / P), __ldg(&Wcls[k * OUTC + t]), a);
        out[t] = a;
    }
}

// =====================================================================
extern "C" void kernel_launch(void* const* d_in, const int* in_sizes, int n_in,
                              void* d_out, int out_size) {
    const float* patch_feats = (const float*)d_in[0];
    const int*   patch_src   = (const int*)d_in[1];
    const int*   patch_dst   = (const int*)d_in[2];
    const float* patch_ew    = (const float*)d_in[3];
    const int*   mesh_src    = (const int*)d_in[4];
    const int*   mesh_dst    = (const int*)d_in[5];
    const float* mesh_ew     = (const float*)d_in[6];
    const float* W1  = (const float*)d_in[7];
    const float* g1  = (const float*)d_in[8];
    const float* b1  = (const float*)d_in[9];
    const float* W2  = (const float*)d_in[10];
    const float* g2  = (const float*)d_in[11];
    const float* b2  = (const float*)d_in[12];
    const float* We  = (const float*)d_in[13];
    const float* Wc1 = (const float*)d_in[14];
    const float* g3  = (const float*)d_in[15];
    const float* b3  = (const float*)d_in[16];
    const float* Wc2 = (const float*)d_in[17];
    const float* g4  = (const float*)d_in[18];
    const float* b4  = (const float*)d_in[19];
    const float* Wcls = (const float*)d_in[20];
    float* out = (float*)d_out;

    cudaFuncSetAttribute(patch_kernel, cudaFuncAttributeMaxDynamicSharedMemorySize, SMEM_PATCH);

    void *pEmb, *pAgg1, *pAgg2, *pH, *pH2;
    cudaGetSymbolAddress(&pEmb,  gEmb);
    cudaGetSymbolAddress(&pAgg1, gAgg1);
    cudaGetSymbolAddress(&pAgg2, gAgg2);
    cudaGetSymbolAddress(&pH,    gH);
    cudaGetSymbolAddress(&pH2,   gH2);

    // keep patch_kernel as 4th launch so ncu's window lands on it
    init_zero<<<(P + 255) / 256, 256>>>();
    mesh_deg<<<(EM + 255) / 256, 256>>>(mesh_src, mesh_dst);
    mesh_rs<<<(P + 255) / 256, 256>>>();

    patch_kernel<<<P, TPB, SMEM_PATCH>>>(patch_feats, patch_src, patch_dst, patch_ew,
                                         W1, g1, b1, W2, g2, b2, We);

    mesh_scan<<<1, 256>>>();
    mesh_sort<<<(EM + 255) / 256, 256>>>(mesh_src, mesh_dst, mesh_ew);

    // mesh conv1 (stats fused into gemm)
    mesh_gather128<<<P / 8, 256>>>((const float*)pEmb, (float*)pAgg1);
    mesh_gemm<RD><<<P / 16, 256>>>((const float*)pAgg1, Wc1, (float*)pH, 0);
    mesh_finalize<<<1, 256>>>(g3, b3, 0);
    mesh_apply<<<P / 50, 256>>>((float*)pH, 0);

    // mesh conv2 (stats fused into gemm)
    mesh_gather256<<<P / 4, 256>>>((const float*)pH, (float*)pAgg2);
    mesh_gemm<HM><<<P / 16, 256>>>((const float*)pAgg2, Wc2, (float*)pH2, HM);
    mesh_finalize<<<1, 256>>>(g4, b4, HM);
    mesh_apply<<<P / 50, 256>>>((float*)pH2, HM);

    final_kernel<<<1, 32>>>(Wcls, out);
}